// round 1
// baseline (speedup 1.0000x reference)
#include <cuda_runtime.h>
#include <cstdint>

// Problem dims
#define Bm   32
#define Dm   2560
#define Em   5120
#define RK   160
#define STn  16
#define BE   (Bm*Em)      // 163840
#define BD   (Bm*Dm)      // 81920

// -------- scratch (static device globals; no runtime allocation) ----------
__device__ float g_p_ssm[4 * BE];      // split-K partials for x@W_in_ssm
__device__ float g_p_mlp[4 * BE];      // split-K partials for x@W_in_mlp
__device__ float g_xt   [BE];          // silu(conv)
__device__ float g_res  [BE];          // silu(x@W_in_mlp)
__device__ float g_dbcp [8 * Bm * 192];// dbc split-K partials
__device__ float g_dbc  [Bm * 192];    // dbc reduced
__device__ float g_z    [BE];          // y * residual
__device__ float g_p_out[8 * BD];      // split-K partials for final GEMM

// -------- f32x2 helpers ----------
__device__ __forceinline__ unsigned long long pack2(float x, float y) {
    unsigned long long r;
    asm("mov.b64 %0, {%1,%2};" : "=l"(r) : "f"(x), "f"(y));
    return r;
}
__device__ __forceinline__ void fma2(unsigned long long& d,
                                     unsigned long long a,
                                     unsigned long long b) {
    asm("fma.rn.f32x2 %0, %1, %2, %0;" : "+l"(d) : "l"(a), "l"(b));
}
__device__ __forceinline__ float2 unpack2(unsigned long long v) {
    float2 r;
    asm("mov.b64 {%0,%1}, %2;" : "=f"(r.x), "=f"(r.y) : "l"(v));
    return r;
}

__device__ __forceinline__ float silu_f(float v) {
    return v * (1.0f / (1.0f + expf(-v)));
}

// ---------------------------------------------------------------------------
// gemm32: C_partial[ks] = X(32,KTOT slice) @ W(KTOT, NCOLS) over a K split.
// Block: 256 threads, N-tile = 128 columns, all 32 rows.
// Micro-tile per thread: 4 rows x 4 cols using f32x2 FMAs.
// SRC: 0 -> X param, 1 -> g_z.   DST: 0 -> g_p_ssm, 1 -> g_p_mlp, 2 -> g_p_out
// ---------------------------------------------------------------------------
template <int KTOT, int KSPLIT, int NCOLS, int XSTRIDE, int SRC, int DST>
__global__ __launch_bounds__(256)
void gemm32(const float* __restrict__ X, const float* __restrict__ W) {
    __shared__ unsigned long long Xs2[32][33];  // [kk][b], duplicated lanes
    __shared__ float Ws[32][128];               // [kk][n]

    const float* Xp = (SRC == 0) ? X : g_z;
    float* part = (DST == 0) ? g_p_ssm : (DST == 1) ? g_p_mlp : g_p_out;

    const int t  = threadIdx.x;
    const int n0 = blockIdx.x * 128;
    constexpr int KPER = KTOT / KSPLIT;
    const int kbase = blockIdx.y * KPER;
    const int b0 = (t >> 5) * 4;   // 8 row-groups of 4
    const int nq = (t & 31) * 4;   // 32 col-groups of 4

    unsigned long long acc[4][2];
#pragma unroll
    for (int j = 0; j < 4; j++) { acc[j][0] = 0ULL; acc[j][1] = 0ULL; }

    for (int kc = 0; kc < KPER; kc += 32) {
        const int kg = kbase + kc;
        // stage X (32 rows x 32 k) duplicated into both f32x2 lanes
#pragma unroll
        for (int i = t; i < 1024; i += 256) {
            int b = i >> 5, kk = i & 31;
            float v = Xp[b * XSTRIDE + kg + kk];
            Xs2[kk][b] = pack2(v, v);
        }
        // stage W (32 k x 128 n)
#pragma unroll
        for (int i = t; i < 1024; i += 256) {
            int kk = i >> 5, c4 = i & 31;
            float4 w = *reinterpret_cast<const float4*>(
                &W[(size_t)(kg + kk) * NCOLS + n0 + c4 * 4]);
            *reinterpret_cast<float4*>(&Ws[kk][c4 * 4]) = w;
        }
        __syncthreads();
#pragma unroll
        for (int kk = 0; kk < 32; kk++) {
            float4 w = *reinterpret_cast<const float4*>(&Ws[kk][nq]);
            unsigned long long w01 = pack2(w.x, w.y);
            unsigned long long w23 = pack2(w.z, w.w);
#pragma unroll
            for (int j = 0; j < 4; j++) {
                unsigned long long xa = Xs2[kk][b0 + j];
                fma2(acc[j][0], xa, w01);
                fma2(acc[j][1], xa, w23);
            }
        }
        __syncthreads();
    }
#pragma unroll
    for (int j = 0; j < 4; j++) {
        float2 p0 = unpack2(acc[j][0]);
        float2 p1 = unpack2(acc[j][1]);
        float4 o = make_float4(p0.x, p0.y, p1.x, p1.y);
        *reinterpret_cast<float4*>(
            &part[((size_t)blockIdx.y * Bm + b0 + j) * NCOLS + n0 + nq]) = o;
    }
}

// ---------------------------------------------------------------------------
// Reduce split-K partials of both input GEMMs, apply depthwise conv + SiLU.
// ---------------------------------------------------------------------------
__global__ __launch_bounds__(256)
void conv_silu_kernel(const float* __restrict__ conv_w,
                      const float* __restrict__ conv_b,
                      const float* __restrict__ conv_states) {
    int idx = blockIdx.x * 256 + threadIdx.x;  // [0, BE)
    float xssm = g_p_ssm[idx] + g_p_ssm[idx + BE] + g_p_ssm[idx + 2 * BE] +
                 g_p_ssm[idx + 3 * BE];
    float xmlp = g_p_mlp[idx] + g_p_mlp[idx + BE] + g_p_mlp[idx + 2 * BE] +
                 g_p_mlp[idx + 3 * BE];
    float c = conv_b[idx];
    c += conv_states[idx]          * conv_w[idx];
    c += conv_states[idx + BE]     * conv_w[idx + BE];
    c += conv_states[idx + 2 * BE] * conv_w[idx + 2 * BE];
    c += xssm                      * conv_w[idx + 3 * BE];
    g_xt[idx]  = silu_f(c);
    g_res[idx] = silu_f(xmlp);
}

// ---------------------------------------------------------------------------
// dbc = xt(32,5120) @ Wx(5120,192), split-K = 8.
// Block: 256 threads = 64 n-cols x 4 batch-groups(8 rows each).
// grid: (3 n-tiles, 8 k-splits)
// ---------------------------------------------------------------------------
__global__ __launch_bounds__(256)
void dbc_partial_kernel(const float* __restrict__ Wx) {
    const int nl = threadIdx.x & 63;
    const int bg = threadIdx.x >> 6;         // 0..3
    const int n  = blockIdx.x * 64 + nl;     // < 192
    const int k0 = blockIdx.y * 640;
    const int b0 = bg * 8;

    float acc[8];
#pragma unroll
    for (int j = 0; j < 8; j++) acc[j] = 0.0f;

    for (int k = k0; k < k0 + 640; k++) {
        float w = Wx[(size_t)k * 192 + n];
#pragma unroll
        for (int j = 0; j < 8; j++)
            acc[j] += g_xt[(b0 + j) * Em + k] * w;
    }
#pragma unroll
    for (int j = 0; j < 8; j++)
        g_dbcp[((size_t)blockIdx.y * Bm + b0 + j) * 192 + n] = acc[j];
}

__global__ void dbc_reduce_kernel() {
    int i = blockIdx.x * 256 + threadIdx.x;  // [0, 6144)
    float s = 0.0f;
#pragma unroll
    for (int ks = 0; ks < 8; ks++) s += g_dbcp[ks * Bm * 192 + i];
    g_dbc[i] = s;
}

// ---------------------------------------------------------------------------
// dt = softplus(dbc[:, :160] @ W_dt + dt_bias); full SSM update; z = y * res.
// Thread handles one e-column for 8 batch rows. grid = 4*5120/256 = 80 blocks.
// ---------------------------------------------------------------------------
__global__ __launch_bounds__(256)
void ssm_kernel(const float* __restrict__ W_dt,
                const float* __restrict__ dt_bias,
                const float* __restrict__ A_log,
                const float* __restrict__ Dv,
                const float* __restrict__ h) {
    int gid = blockIdx.x * 256 + threadIdx.x;  // [0, 4*Em)
    int e  = gid % Em;
    int b0 = (gid / Em) * 8;

    float dtacc[8];
#pragma unroll
    for (int j = 0; j < 8; j++) dtacc[j] = 0.0f;

    for (int k = 0; k < RK; k++) {
        float wd = W_dt[(size_t)k * Em + e];
#pragma unroll
        for (int j = 0; j < 8; j++)
            dtacc[j] += g_dbc[(b0 + j) * 192 + k] * wd;
    }

    float bias = dt_bias[e];
    float dval = Dv[e];
    float An[STn];
#pragma unroll
    for (int n = 0; n < STn; n++) An[n] = -expf(A_log[(size_t)e * STn + n]);

#pragma unroll
    for (int j = 0; j < 8; j++) {
        int b = b0 + j;
        float s = dtacc[j] + bias;
        float dt = (s > 20.0f) ? s : log1pf(expf(s));
        float xt = g_xt[b * Em + e];
        const float* hb = &h[((size_t)b * Em + e) * STn];
        float y = 0.0f;
#pragma unroll
        for (int n = 0; n < STn; n++) {
            float Bv = g_dbc[b * 192 + 160 + n];
            float Cv = g_dbc[b * 192 + 176 + n];
            float dA = expf(dt * An[n]);
            float hn = hb[n] * dA + dt * Bv * xt;
            y += hn * Cv;
        }
        y += dval * xt;
        g_z[b * Em + e] = y * g_res[b * Em + e];
    }
}

__global__ void out_reduce_kernel(float* __restrict__ out) {
    int i = blockIdx.x * 256 + threadIdx.x;  // [0, BD)
    float s = 0.0f;
#pragma unroll
    for (int ks = 0; ks < 8; ks++) s += g_p_out[ks * BD + i];
    out[i] = s;
}

// ---------------------------------------------------------------------------
extern "C" void kernel_launch(void* const* d_in, const int* in_sizes, int n_in,
                              void* d_out, int out_size) {
    const float* x        = (const float*)d_in[0];
    const float* W_in_ssm = (const float*)d_in[1];
    const float* W_in_mlp = (const float*)d_in[2];
    const float* W_out    = (const float*)d_in[3];
    const float* conv_w   = (const float*)d_in[4];
    const float* conv_b   = (const float*)d_in[5];
    const float* conv_st  = (const float*)d_in[6];
    const float* Wx       = (const float*)d_in[7];
    const float* W_dt     = (const float*)d_in[8];
    const float* dt_bias  = (const float*)d_in[9];
    const float* A_log    = (const float*)d_in[10];
    const float* Dvec     = (const float*)d_in[11];
    const float* h        = (const float*)d_in[12];
    float* out = (float*)d_out;

    // 1,2: x @ W_in_ssm and x @ W_in_mlp (split-K = 4)
    gemm32<2560, 4, 5120, 2560, 0, 0><<<dim3(40, 4), 256>>>(x, W_in_ssm);
    gemm32<2560, 4, 5120, 2560, 0, 1><<<dim3(40, 4), 256>>>(x, W_in_mlp);
    // 3: reduce + conv + silu
    conv_silu_kernel<<<BE / 256, 256>>>(conv_w, conv_b, conv_st);
    // 4,5: dbc projection
    dbc_partial_kernel<<<dim3(3, 8), 256>>>(Wx);
    dbc_reduce_kernel<<<24, 256>>>();
    // 6: dt GEMM + softplus + SSM scan + y*residual
    ssm_kernel<<<80, 256>>>(W_dt, dt_bias, A_log, Dvec, h);
    // 7,8: final GEMM (split-K = 8) + reduce
    gemm32<5120, 8, 2560, 5120, 1, 2><<<dim3(20, 8), 256>>>(nullptr, W_out);
    out_reduce_kernel<<<BD / 256, 256>>>(out);
}

// round 2
// speedup vs baseline: 1.9356x; 1.9356x over previous
#include <cuda_runtime.h>
#include <cstdint>

// Problem dims
#define Bm   32
#define Dm   2560
#define Em   5120
#define RK   160
#define STn  16
#define BE   (Bm*Em)      // 163840
#define BD   (Bm*Dm)      // 81920
#define KS_IN   8         // split-K for input GEMMs
#define KS_OUT  16        // split-K for output GEMM
#define KS_DBC  40        // split-K for dbc projection

// -------- scratch (static device globals; no runtime allocation) ----------
__device__ float g_p_ssm[KS_IN * BE];
__device__ float g_p_mlp[KS_IN * BE];
__device__ float g_xt   [BE];
__device__ float g_res  [BE];
__device__ float g_dbcp [KS_DBC * Bm * 192];
__device__ float g_dbc  [Bm * 192];
__device__ float g_z    [BE];
__device__ float g_p_out[KS_OUT * BD];

// -------- f32x2 helpers ----------
__device__ __forceinline__ unsigned long long pack2(float x, float y) {
    unsigned long long r;
    asm("mov.b64 %0, {%1,%2};" : "=l"(r) : "f"(x), "f"(y));
    return r;
}
__device__ __forceinline__ void fma2(unsigned long long& d,
                                     unsigned long long a,
                                     unsigned long long b) {
    asm("fma.rn.f32x2 %0, %1, %2, %0;" : "+l"(d) : "l"(a), "l"(b));
}
__device__ __forceinline__ float2 unpack2(unsigned long long v) {
    float2 r;
    asm("mov.b64 {%0,%1}, %2;" : "=f"(r.x), "=f"(r.y) : "l"(v));
    return r;
}

__device__ __forceinline__ float silu_f(float v) {
    return v * (1.0f / (1.0f + expf(-v)));
}

// ---------------------------------------------------------------------------
// gemm32: C_partial[ks] = X(32,K slice) @ W(K, NCOLS).
// Block: 256 threads, N-tile 128, all 32 rows; 4x4 micro-tile via f32x2.
// ---------------------------------------------------------------------------
template <int KTOT, int KSPLIT, int NCOLS, int XSTRIDE, int SRC, int DST>
__global__ __launch_bounds__(256)
void gemm32(const float* __restrict__ X, const float* __restrict__ W) {
    __shared__ unsigned long long Xs2[32][33];
    __shared__ float Ws[32][128];

    const float* Xp = (SRC == 0) ? X : g_z;
    float* part = (DST == 0) ? g_p_ssm : (DST == 1) ? g_p_mlp : g_p_out;

    const int t  = threadIdx.x;
    const int n0 = blockIdx.x * 128;
    constexpr int KPER = KTOT / KSPLIT;
    const int kbase = blockIdx.y * KPER;
    const int b0 = (t >> 5) * 4;
    const int nq = (t & 31) * 4;

    unsigned long long acc[4][2];
#pragma unroll
    for (int j = 0; j < 4; j++) { acc[j][0] = 0ULL; acc[j][1] = 0ULL; }

    for (int kc = 0; kc < KPER; kc += 32) {
        const int kg = kbase + kc;
#pragma unroll
        for (int i = t; i < 1024; i += 256) {
            int b = i >> 5, kk = i & 31;
            float v = Xp[b * XSTRIDE + kg + kk];
            Xs2[kk][b] = pack2(v, v);
        }
#pragma unroll
        for (int i = t; i < 1024; i += 256) {
            int kk = i >> 5, c4 = i & 31;
            float4 w = *reinterpret_cast<const float4*>(
                &W[(size_t)(kg + kk) * NCOLS + n0 + c4 * 4]);
            *reinterpret_cast<float4*>(&Ws[kk][c4 * 4]) = w;
        }
        __syncthreads();
#pragma unroll
        for (int kk = 0; kk < 32; kk++) {
            float4 w = *reinterpret_cast<const float4*>(&Ws[kk][nq]);
            unsigned long long w01 = pack2(w.x, w.y);
            unsigned long long w23 = pack2(w.z, w.w);
#pragma unroll
            for (int j = 0; j < 4; j++) {
                unsigned long long xa = Xs2[kk][b0 + j];
                fma2(acc[j][0], xa, w01);
                fma2(acc[j][1], xa, w23);
            }
        }
        __syncthreads();
    }
#pragma unroll
    for (int j = 0; j < 4; j++) {
        float2 p0 = unpack2(acc[j][0]);
        float2 p1 = unpack2(acc[j][1]);
        float4 o = make_float4(p0.x, p0.y, p1.x, p1.y);
        *reinterpret_cast<float4*>(
            &part[((size_t)blockIdx.y * Bm + b0 + j) * NCOLS + n0 + nq]) = o;
    }
}

// ---------------------------------------------------------------------------
// Reduce split-K partials of both input GEMMs, depthwise conv + SiLU.
// ---------------------------------------------------------------------------
__global__ __launch_bounds__(256)
void conv_silu_kernel(const float* __restrict__ conv_w,
                      const float* __restrict__ conv_b,
                      const float* __restrict__ conv_states) {
    int idx = blockIdx.x * 256 + threadIdx.x;
    float xssm = 0.0f, xmlp = 0.0f;
#pragma unroll
    for (int ks = 0; ks < KS_IN; ks++) {
        xssm += g_p_ssm[idx + ks * BE];
        xmlp += g_p_mlp[idx + ks * BE];
    }
    float c = conv_b[idx];
    c += conv_states[idx]          * conv_w[idx];
    c += conv_states[idx + BE]     * conv_w[idx + BE];
    c += conv_states[idx + 2 * BE] * conv_w[idx + 2 * BE];
    c += xssm                      * conv_w[idx + 3 * BE];
    g_xt[idx]  = silu_f(c);
    g_res[idx] = silu_f(xmlp);
}

// ---------------------------------------------------------------------------
// dbc = xt(32,5120) @ Wx(5120,192), split-K = 40 (KPER=128).
// Block: 256 threads = 64 n-cols x 4 batch-groups(8 rows). grid (3, 40).
// ---------------------------------------------------------------------------
__global__ __launch_bounds__(256)
void dbc_partial_kernel(const float* __restrict__ Wx) {
    const int nl = threadIdx.x & 63;
    const int bg = threadIdx.x >> 6;
    const int n  = blockIdx.x * 64 + nl;
    const int k0 = blockIdx.y * (Em / KS_DBC);   // 128 per split
    const int b0 = bg * 8;

    float acc[8];
#pragma unroll
    for (int j = 0; j < 8; j++) acc[j] = 0.0f;

#pragma unroll 4
    for (int k = k0; k < k0 + Em / KS_DBC; k++) {
        float w = Wx[(size_t)k * 192 + n];
#pragma unroll
        for (int j = 0; j < 8; j++)
            acc[j] += g_xt[(b0 + j) * Em + k] * w;
    }
#pragma unroll
    for (int j = 0; j < 8; j++)
        g_dbcp[((size_t)blockIdx.y * Bm + b0 + j) * 192 + n] = acc[j];
}

__global__ void dbc_reduce_kernel() {
    int i = blockIdx.x * 256 + threadIdx.x;  // [0, 6144)
    float s = 0.0f;
#pragma unroll
    for (int ks = 0; ks < KS_DBC; ks++) s += g_dbcp[ks * Bm * 192 + i];
    g_dbc[i] = s;
}

// ---------------------------------------------------------------------------
// dt = softplus(dbc[:, :160] @ W_dt + dt_bias); SSM update; z = y * res.
// Thread handles one e-column for 4 batch rows. grid = 8*Em/256 = 160 blocks.
// ---------------------------------------------------------------------------
__global__ __launch_bounds__(256)
void ssm_kernel(const float* __restrict__ W_dt,
                const float* __restrict__ dt_bias,
                const float* __restrict__ A_log,
                const float* __restrict__ Dv,
                const float* __restrict__ h) {
    int gid = blockIdx.x * 256 + threadIdx.x;  // [0, 8*Em)
    int e  = gid % Em;
    int b0 = (gid / Em) * 4;

    float dtacc[4];
#pragma unroll
    for (int j = 0; j < 4; j++) dtacc[j] = 0.0f;

#pragma unroll 4
    for (int k = 0; k < RK; k++) {
        float wd = W_dt[(size_t)k * Em + e];
#pragma unroll
        for (int j = 0; j < 4; j++)
            dtacc[j] += g_dbc[(b0 + j) * 192 + k] * wd;
    }

    float bias = dt_bias[e];
    float dval = Dv[e];
    float An[STn];
#pragma unroll
    for (int n = 0; n < STn; n++) An[n] = -expf(A_log[(size_t)e * STn + n]);

#pragma unroll
    for (int j = 0; j < 4; j++) {
        int b = b0 + j;
        float s = dtacc[j] + bias;
        float dt = (s > 20.0f) ? s : log1pf(expf(s));
        float xt = g_xt[b * Em + e];
        const float* hb = &h[((size_t)b * Em + e) * STn];
        float y = 0.0f;
#pragma unroll
        for (int n = 0; n < STn; n++) {
            float Bv = g_dbc[b * 192 + 160 + n];
            float Cv = g_dbc[b * 192 + 176 + n];
            float dA = expf(dt * An[n]);
            float hn = hb[n] * dA + dt * Bv * xt;
            y += hn * Cv;
        }
        y += dval * xt;
        g_z[b * Em + e] = y * g_res[b * Em + e];
    }
}

__global__ void out_reduce_kernel(float* __restrict__ out) {
    int i = blockIdx.x * 256 + threadIdx.x;  // [0, BD)
    float s = 0.0f;
#pragma unroll
    for (int ks = 0; ks < KS_OUT; ks++) s += g_p_out[ks * BD + i];
    out[i] = s;
}

// ---------------------------------------------------------------------------
extern "C" void kernel_launch(void* const* d_in, const int* in_sizes, int n_in,
                              void* d_out, int out_size) {
    const float* x        = (const float*)d_in[0];
    const float* W_in_ssm = (const float*)d_in[1];
    const float* W_in_mlp = (const float*)d_in[2];
    const float* W_out    = (const float*)d_in[3];
    const float* conv_w   = (const float*)d_in[4];
    const float* conv_b   = (const float*)d_in[5];
    const float* conv_st  = (const float*)d_in[6];
    const float* Wx       = (const float*)d_in[7];
    const float* W_dt     = (const float*)d_in[8];
    const float* dt_bias  = (const float*)d_in[9];
    const float* A_log    = (const float*)d_in[10];
    const float* Dvec     = (const float*)d_in[11];
    const float* h        = (const float*)d_in[12];
    float* out = (float*)d_out;

    gemm32<2560, KS_IN, 5120, 2560, 0, 0><<<dim3(40, KS_IN), 256>>>(x, W_in_ssm);
    gemm32<2560, KS_IN, 5120, 2560, 0, 1><<<dim3(40, KS_IN), 256>>>(x, W_in_mlp);
    conv_silu_kernel<<<BE / 256, 256>>>(conv_w, conv_b, conv_st);
    dbc_partial_kernel<<<dim3(3, KS_DBC), 256>>>(Wx);
    dbc_reduce_kernel<<<24, 256>>>();
    ssm_kernel<<<160, 256>>>(W_dt, dt_bias, A_log, Dvec, h);
    gemm32<5120, KS_OUT, 2560, 5120, 1, 2><<<dim3(20, KS_OUT), 256>>>(nullptr, W_out);
    out_reduce_kernel<<<BD / 256, 256>>>(out);
}

// round 3
// speedup vs baseline: 2.4931x; 1.2880x over previous
#include <cuda_runtime.h>
#include <cstdint>

#define Bm   32
#define Dm   2560
#define Em   5120
#define RK   160
#define STn  16
#define BE   (Bm*Em)
#define BD   (Bm*Dm)
#define KS_IN   16
#define KS_OUT  32
#define KS_DBC  40

// -------- scratch ----------
__device__ float g_p_ssm[KS_IN * BE];
__device__ float g_p_mlp[KS_IN * BE];
__device__ float g_xt   [BE];
__device__ float g_res  [BE];
__device__ float g_dbcp [KS_DBC * Bm * 192];
__device__ float g_dbc  [Bm * 192];
__device__ float g_z    [BE];
__device__ float g_p_out[KS_OUT * BD];

// -------- f32x2 helpers ----------
__device__ __forceinline__ unsigned long long pack2(float x, float y) {
    unsigned long long r;
    asm("mov.b64 %0, {%1,%2};" : "=l"(r) : "f"(x), "f"(y));
    return r;
}
__device__ __forceinline__ void fma2(unsigned long long& d,
                                     unsigned long long a,
                                     unsigned long long b) {
    asm("fma.rn.f32x2 %0, %1, %2, %0;" : "+l"(d) : "l"(a), "l"(b));
}
__device__ __forceinline__ float2 unpack2(unsigned long long v) {
    float2 r;
    asm("mov.b64 {%0,%1}, %2;" : "=f"(r.x), "=f"(r.y) : "l"(v));
    return r;
}
__device__ __forceinline__ float silu_f(float v) {
    return v * (1.0f / (1.0f + expf(-v)));
}

// ---------------------------------------------------------------------------
// gemm32b: 32-row GEMM, N-tile 128, 128 threads, micro 4 rows x 8 cols (f32x2).
// W pre-packed into f32x2 pairs at staging.
// ---------------------------------------------------------------------------
template <int KTOT, int KSPLIT, int NCOLS, int XSTRIDE, int SRC, int DST>
__global__ __launch_bounds__(128)
void gemm32b(const float* __restrict__ X, const float* __restrict__ W) {
    __shared__ unsigned long long Xs2[32][33];  // [kk][b] duplicated lanes
    __shared__ unsigned long long Ws2[32][64];  // [kk][col-pair]

    const float* Xp = (SRC == 0) ? X : g_z;
    float* part = (DST == 0) ? g_p_ssm : (DST == 1) ? g_p_mlp : g_p_out;

    const int t  = threadIdx.x;
    const int n0 = blockIdx.x * 128;
    constexpr int KPER = KTOT / KSPLIT;
    const int kbase = blockIdx.y * KPER;
    const int cg = t & 15;          // 16 col-groups of 8 cols
    const int rg = t >> 4;          // 8 row-groups of 4 rows
    const int b0 = rg * 4;
    const int qu = cg * 4;          // first ull index of this thread's cols

    unsigned long long acc[4][4];
#pragma unroll
    for (int j = 0; j < 4; j++)
#pragma unroll
        for (int q = 0; q < 4; q++) acc[j][q] = 0ULL;

    for (int kc = 0; kc < KPER; kc += 32) {
        const int kg = kbase + kc;
        // stage X (32 b x 32 k), duplicate into both f32x2 lanes
#pragma unroll
        for (int i = t; i < 1024; i += 128) {
            int b = i >> 5, kk = i & 31;
            float v = Xp[b * XSTRIDE + kg + kk];
            Xs2[kk][b] = pack2(v, v);
        }
        // stage W (32 k x 128 n) pre-packed
#pragma unroll
        for (int i = t; i < 1024; i += 128) {
            int kk = i >> 5, c4 = i & 31;
            float4 w = *reinterpret_cast<const float4*>(
                &W[(size_t)(kg + kk) * NCOLS + n0 + c4 * 4]);
            Ws2[kk][c4 * 2]     = pack2(w.x, w.y);
            Ws2[kk][c4 * 2 + 1] = pack2(w.z, w.w);
        }
        __syncthreads();
#pragma unroll
        for (int kk = 0; kk < 32; kk++) {
            unsigned long long w0 = Ws2[kk][qu];
            unsigned long long w1 = Ws2[kk][qu + 1];
            unsigned long long w2 = Ws2[kk][qu + 2];
            unsigned long long w3 = Ws2[kk][qu + 3];
#pragma unroll
            for (int j = 0; j < 4; j++) {
                unsigned long long xa = Xs2[kk][b0 + j];
                fma2(acc[j][0], xa, w0);
                fma2(acc[j][1], xa, w1);
                fma2(acc[j][2], xa, w2);
                fma2(acc[j][3], xa, w3);
            }
        }
        __syncthreads();
    }
#pragma unroll
    for (int j = 0; j < 4; j++) {
        float2 a0 = unpack2(acc[j][0]);
        float2 a1 = unpack2(acc[j][1]);
        float2 a2 = unpack2(acc[j][2]);
        float2 a3 = unpack2(acc[j][3]);
        float* dst = &part[((size_t)blockIdx.y * Bm + b0 + j) * NCOLS + n0 + cg * 8];
        *reinterpret_cast<float4*>(dst)     = make_float4(a0.x, a0.y, a1.x, a1.y);
        *reinterpret_cast<float4*>(dst + 4) = make_float4(a2.x, a2.y, a3.x, a3.y);
    }
}

// ---------------------------------------------------------------------------
// dbc GEMM: xt(32,5120) @ Wx(5120,192). N-tile 64, 128 threads, micro 4x4.
// grid (3, KS_DBC). KPER = 128 -> 4 chunks of 32.
// ---------------------------------------------------------------------------
__global__ __launch_bounds__(128)
void dbc_gemm_kernel(const float* __restrict__ Wx) {
    __shared__ unsigned long long Xs2[32][33];
    __shared__ unsigned long long Ws2[32][32];  // 64 cols -> 32 ull

    const int t  = threadIdx.x;
    const int n0 = blockIdx.x * 64;
    constexpr int KPER = Em / KS_DBC;  // 128
    const int kbase = blockIdx.y * KPER;
    const int cg = t & 15;     // 16 col-groups of 4 cols
    const int rg = t >> 4;     // 8 row-groups of 4 rows
    const int b0 = rg * 4;
    const int qu = cg * 2;

    unsigned long long acc[4][2];
#pragma unroll
    for (int j = 0; j < 4; j++) { acc[j][0] = 0ULL; acc[j][1] = 0ULL; }

    for (int kc = 0; kc < KPER; kc += 32) {
        const int kg = kbase + kc;
#pragma unroll
        for (int i = t; i < 1024; i += 128) {
            int b = i >> 5, kk = i & 31;
            float v = g_xt[b * Em + kg + kk];
            Xs2[kk][b] = pack2(v, v);
        }
#pragma unroll
        for (int i = t; i < 512; i += 128) {
            int kk = i >> 4, c4 = i & 15;
            float4 w = *reinterpret_cast<const float4*>(
                &Wx[(size_t)(kg + kk) * 192 + n0 + c4 * 4]);
            Ws2[kk][c4 * 2]     = pack2(w.x, w.y);
            Ws2[kk][c4 * 2 + 1] = pack2(w.z, w.w);
        }
        __syncthreads();
#pragma unroll
        for (int kk = 0; kk < 32; kk++) {
            unsigned long long w0 = Ws2[kk][qu];
            unsigned long long w1 = Ws2[kk][qu + 1];
#pragma unroll
            for (int j = 0; j < 4; j++) {
                unsigned long long xa = Xs2[kk][b0 + j];
                fma2(acc[j][0], xa, w0);
                fma2(acc[j][1], xa, w1);
            }
        }
        __syncthreads();
    }
#pragma unroll
    for (int j = 0; j < 4; j++) {
        float2 a0 = unpack2(acc[j][0]);
        float2 a1 = unpack2(acc[j][1]);
        *reinterpret_cast<float4*>(
            &g_dbcp[((size_t)blockIdx.y * Bm + b0 + j) * 192 + n0 + cg * 4]) =
            make_float4(a0.x, a0.y, a1.x, a1.y);
    }
}

// ---------------------------------------------------------------------------
__global__ __launch_bounds__(256)
void conv_silu_kernel(const float* __restrict__ conv_w,
                      const float* __restrict__ conv_b,
                      const float* __restrict__ conv_states) {
    int idx = blockIdx.x * 256 + threadIdx.x;
    float xssm = 0.0f, xmlp = 0.0f;
#pragma unroll
    for (int ks = 0; ks < KS_IN; ks++) {
        xssm += g_p_ssm[idx + ks * BE];
        xmlp += g_p_mlp[idx + ks * BE];
    }
    float c = conv_b[idx];
    c += conv_states[idx]          * conv_w[idx];
    c += conv_states[idx + BE]     * conv_w[idx + BE];
    c += conv_states[idx + 2 * BE] * conv_w[idx + 2 * BE];
    c += xssm                      * conv_w[idx + 3 * BE];
    g_xt[idx]  = silu_f(c);
    g_res[idx] = silu_f(xmlp);
}

__global__ void dbc_reduce_kernel() {
    int i = blockIdx.x * 256 + threadIdx.x;  // [0, 6144)
    float s = 0.0f;
#pragma unroll
    for (int ks = 0; ks < KS_DBC; ks++) s += g_dbcp[ks * Bm * 192 + i];
    g_dbc[i] = s;
}

// ---------------------------------------------------------------------------
// dt GEMM + softplus + SSM update + z = y * res. 2 rows/thread, 320 blocks.
// ---------------------------------------------------------------------------
__global__ __launch_bounds__(256)
void ssm_kernel(const float* __restrict__ W_dt,
                const float* __restrict__ dt_bias,
                const float* __restrict__ A_log,
                const float* __restrict__ Dv,
                const float* __restrict__ h) {
    int gid = blockIdx.x * 256 + threadIdx.x;  // [0, 16*Em)
    int e  = gid % Em;
    int b0 = (gid / Em) * 2;

    float dt0 = 0.0f, dt1 = 0.0f;
#pragma unroll 8
    for (int k = 0; k < RK; k++) {
        float wd = W_dt[(size_t)k * Em + e];
        dt0 += g_dbc[b0 * 192 + k] * wd;
        dt1 += g_dbc[(b0 + 1) * 192 + k] * wd;
    }

    float bias = dt_bias[e];
    float dval = Dv[e];
    float An[STn];
#pragma unroll
    for (int n = 0; n < STn; n++) An[n] = -expf(A_log[(size_t)e * STn + n]);

    float dts[2] = {dt0, dt1};
#pragma unroll
    for (int j = 0; j < 2; j++) {
        int b = b0 + j;
        float s = dts[j] + bias;
        float dt = (s > 20.0f) ? s : log1pf(expf(s));
        float xt = g_xt[b * Em + e];
        const float* hb = &h[((size_t)b * Em + e) * STn];
        float y = 0.0f;
#pragma unroll
        for (int n = 0; n < STn; n++) {
            float Bv = g_dbc[b * 192 + 160 + n];
            float Cv = g_dbc[b * 192 + 176 + n];
            float dA = expf(dt * An[n]);
            float hn = hb[n] * dA + dt * Bv * xt;
            y += hn * Cv;
        }
        y += dval * xt;
        g_z[b * Em + e] = y * g_res[b * Em + e];
    }
}

__global__ void out_reduce_kernel(float* __restrict__ out) {
    int i = blockIdx.x * 256 + threadIdx.x;  // [0, BD)
    float s = 0.0f;
#pragma unroll
    for (int ks = 0; ks < KS_OUT; ks++) s += g_p_out[ks * BD + i];
    out[i] = s;
}

// ---------------------------------------------------------------------------
extern "C" void kernel_launch(void* const* d_in, const int* in_sizes, int n_in,
                              void* d_out, int out_size) {
    const float* x        = (const float*)d_in[0];
    const float* W_in_ssm = (const float*)d_in[1];
    const float* W_in_mlp = (const float*)d_in[2];
    const float* W_out    = (const float*)d_in[3];
    const float* conv_w   = (const float*)d_in[4];
    const float* conv_b   = (const float*)d_in[5];
    const float* conv_st  = (const float*)d_in[6];
    const float* Wx       = (const float*)d_in[7];
    const float* W_dt     = (const float*)d_in[8];
    const float* dt_bias  = (const float*)d_in[9];
    const float* A_log    = (const float*)d_in[10];
    const float* Dvec     = (const float*)d_in[11];
    const float* h        = (const float*)d_in[12];
    float* out = (float*)d_out;

    gemm32b<2560, KS_IN, 5120, 2560, 0, 0><<<dim3(40, KS_IN), 128>>>(x, W_in_ssm);
    gemm32b<2560, KS_IN, 5120, 2560, 0, 1><<<dim3(40, KS_IN), 128>>>(x, W_in_mlp);
    conv_silu_kernel<<<BE / 256, 256>>>(conv_w, conv_b, conv_st);
    dbc_gemm_kernel<<<dim3(3, KS_DBC), 128>>>(Wx);
    dbc_reduce_kernel<<<24, 256>>>();
    ssm_kernel<<<320, 256>>>(W_dt, dt_bias, A_log, Dvec, h);
    gemm32b<5120, KS_OUT, 2560, 5120, 1, 2><<<dim3(20, KS_OUT), 128>>>(nullptr, W_out);
    out_reduce_kernel<<<BD / 256, 256>>>(out);
}